// round 3
// baseline (speedup 1.0000x reference)
#include <cuda_runtime.h>
#include <cstdio>

#define BB 4
#define NSS 96
#define TT 8
#define HD 256
#define H4 1024
#define NN 97
#define NLAY 6
#define ROWS (BB*NN)     // 388
#define SEQS (BB*NSS)    // 384
#define TOK  (SEQS*TT)   // 3072

// ---------------- scratch (static device memory; no runtime allocs) -------
__device__ float g_xw[TOK*H4];        // token @ Wx_s + b_s
__device__ float g_Wt[HD*H4];         // Wh_s gate-interleaved [k][h*4+g]
__device__ float g_c0[SEQS*HD];
__device__ float g_hA[SEQS*HD];       // statement LSTM h ping
__device__ float g_hB[SEQS*HD];       // statement LSTM h pong
__device__ float g_pref[ROWS*HD];     // prefix sums, [B,97,H]
__device__ float g_Me[HD*H4];         // W_se @ Wx_e
__device__ float g_Ms[HD*HD];         // W_se @ W_sd
__device__ float g_be[H4];            // b_se@Wx_e + b_e
__device__ float g_bs[HD];            // b_se@W_sd + b_sd
__device__ float g_pm4[ROWS*H4];      // pref @ Me
__device__ float g_prefS[ROWS*HD];    // pref @ Ms
__device__ float g_S2[BB*NN*NN];      // layer-invariant logit part
__device__ float g_u[ROWS*H4];        // h @ Wh_e + be - pm4
__device__ float g_w[BB*NN*NN];       // skip_p * p[i]
__device__ float g_cX[ROWS*HD], g_hX[ROWS*HD];
__device__ float g_cY[ROWS*HD], g_hY[ROWS*HD];
__device__ float g_pX[ROWS], g_pY[ROWS];

__device__ __forceinline__ float sigf(float x)  { return 1.0f / (1.0f + __expf(-x)); }
__device__ __forceinline__ float tanhr(float x) { return 2.0f / (1.0f + __expf(-2.0f * x)) - 1.0f; }

// ---------------- templated fp32 tiled GEMM ---------------------------------
// C[M,N] = gather(A)[M,K] @ B[K,N] (+bias[N]) (+addScale*addM[M,addStride])
// requires: K % BK == 0, K % 4 == 0, N % BN == 0, 256 threads.
template<int BM, int BN, int BK, int TM, int TN>
__global__ void gemm_t(const float* __restrict__ A, const int* __restrict__ gidx,
                       const float* __restrict__ B, const float* __restrict__ bias,
                       const float* __restrict__ addM, int addStride, float addScale,
                       float* __restrict__ C, int M, int K, int N) {
    constexpr int TX = BN / TN;
    constexpr int TY = BM / TM;
    static_assert(TX * TY == 256, "256 threads");
    __shared__ float sA[BK][BM + 4];
    __shared__ float sB[BK][BN];
    const int tid = threadIdx.x;
    const int tx = tid % TX, ty = tid / TX;
    const int bm = blockIdx.x * BM, bn = blockIdx.y * BN;
    float acc[TM][TN] = {};
    for (int k0 = 0; k0 < K; k0 += BK) {
        constexpr int A4 = BM * BK / 4;
        for (int l = tid; l < A4; l += 256) {
            int r = l / (BK / 4);
            int kc = (l % (BK / 4)) * 4;
            int row = bm + r;
            float4 v = make_float4(0.f, 0.f, 0.f, 0.f);
            if (row < M) {
                int ar = gidx ? gidx[row] : row;
                v = *(const float4*)(A + (size_t)ar * K + k0 + kc);
            }
            sA[kc + 0][r] = v.x; sA[kc + 1][r] = v.y;
            sA[kc + 2][r] = v.z; sA[kc + 3][r] = v.w;
        }
        constexpr int B4 = BK * BN / 4;
        for (int l = tid; l < B4; l += 256) {
            int kk = l / (BN / 4);
            int c = (l % (BN / 4)) * 4;
            *(float4*)(&sB[kk][c]) = *(const float4*)(B + (size_t)(k0 + kk) * N + bn + c);
        }
        __syncthreads();
#pragma unroll
        for (int kk = 0; kk < BK; kk++) {
            float a[TM], b[TN];
#pragma unroll
            for (int i = 0; i < TM; i++) a[i] = sA[kk][ty * TM + i];
#pragma unroll
            for (int j = 0; j < TN; j += 4) {
                float4 v = *(const float4*)(&sB[kk][tx * TN + j]);
                b[j] = v.x; b[j + 1] = v.y; b[j + 2] = v.z; b[j + 3] = v.w;
            }
#pragma unroll
            for (int i = 0; i < TM; i++)
#pragma unroll
                for (int j = 0; j < TN; j++)
                    acc[i][j] += a[i] * b[j];
        }
        __syncthreads();
    }
#pragma unroll
    for (int i = 0; i < TM; i++) {
        int row = bm + ty * TM + i;
        if (row >= M) continue;
#pragma unroll
        for (int j = 0; j < TN; j++) {
            int col = bn + tx * TN + j;
            float v = acc[i][j];
            if (bias) v += bias[col];
            if (addM) v += addScale * addM[(size_t)row * addStride + col];
            C[(size_t)row * N + col] = v;
        }
    }
}

// ---------------- Wh_s -> gate-interleaved layout ---------------------------
__global__ void wt_kernel(const float* __restrict__ Wh, float* __restrict__ Wt) {
    int idx = blockIdx.x * 256 + threadIdx.x;
    if (idx >= HD * H4) return;
    int k = idx / H4, col = idx % H4;        // col = g*256 + h
    int g = col / HD, hh = col % HD;
    Wt[(size_t)k * H4 + hh * 4 + g] = Wh[idx];
}

// ---------------- statement LSTM gate (step 0: z = xw) ----------------------
__global__ void lstm_gate0_kernel(const float* __restrict__ z, int zstride,
                                  float* __restrict__ c, float* __restrict__ h) {
    int idx = blockIdx.x * blockDim.x + threadIdx.x;
    if (idx >= SEQS * HD) return;
    int s = idx / HD, hh = idx % HD;
    const float* zr = z + (size_t)s * zstride;
    float zi = zr[hh], zf = zr[HD + hh], zg = zr[2 * HD + hh], zo = zr[3 * HD + hh];
    float c2 = sigf(zi) * tanhr(zg);   // c_prev = 0
    (void)zf;
    h[idx] = sigf(zo) * tanhr(c2);
    c[idx] = c2;
}

// ---------------- fused recurrent LSTM step ---------------------------------
// grid (SEQS/16, HD/32), 256 threads. z = h_in @ Wh_s + xw[:,t]; gate epilogue.
__global__ void lstm_step_kernel(const float* __restrict__ hin, const float* __restrict__ Wt,
                                 const float* __restrict__ xw_t,
                                 float* __restrict__ c_st, float* __restrict__ hout) {
    __shared__ float sA[16][16 + 1];
    __shared__ float sW[16][128];
    int tid = threadIdx.x;
    int tx = tid % 16;          // h pair index
    int ty = tid / 16;          // row within tile
    int bm = blockIdx.x * 16, bh = blockIdx.y * 32;
    float acc0[4] = {}, acc1[4] = {};
    for (int k0 = 0; k0 < HD; k0 += 16) {
        {
            int r = tid / 16, kk = tid % 16;
            sA[kk][r] = hin[(size_t)(bm + r) * HD + k0 + kk];
        }
#pragma unroll
        for (int l = 0; l < 2; l++) {
            int e = tid + l * 256;          // 512 float4 total
            int kk = e / 32;
            int c = (e % 32) * 4;
            *(float4*)(&sW[kk][c]) = *(const float4*)(Wt + (size_t)(k0 + kk) * H4 + bh * 4 + c);
        }
        __syncthreads();
#pragma unroll
        for (int kk = 0; kk < 16; kk++) {
            float a = sA[kk][ty];
            float4 w0 = *(const float4*)(&sW[kk][(tx * 2 + 0) * 4]);
            float4 w1 = *(const float4*)(&sW[kk][(tx * 2 + 1) * 4]);
            acc0[0] += a * w0.x; acc0[1] += a * w0.y; acc0[2] += a * w0.z; acc0[3] += a * w0.w;
            acc1[0] += a * w1.x; acc1[1] += a * w1.y; acc1[2] += a * w1.z; acc1[3] += a * w1.w;
        }
        __syncthreads();
    }
    int row = bm + ty;
    const float* xr = xw_t + (size_t)row * (TT * H4);
#pragma unroll
    for (int u = 0; u < 2; u++) {
        float* accp = u ? acc1 : acc0;
        int hh = bh + tx * 2 + u;
        float zi = accp[0] + xr[hh];
        float zf = accp[1] + xr[HD + hh];
        float zg = accp[2] + xr[2 * HD + hh];
        float zo = accp[3] + xr[3 * HD + hh];
        size_t idx = (size_t)row * HD + hh;
        float cp = c_st[idx];
        float c2 = sigf(zf) * cp + sigf(zi) * tanhr(zg);
        c_st[idx] = c2;
        hout[idx] = sigf(zo) * tanhr(c2);
    }
}

// ---------------- prefix sums over statements -------------------------------
__global__ void cumsum_kernel(const float* __restrict__ stmt, float* __restrict__ pref) {
    int b = blockIdx.x, hh = threadIdx.x;
    float acc = 0.f;
    pref[(size_t)(b * NN) * HD + hh] = 0.f;
    for (int k = 1; k < NN; k++) {
        acc += stmt[(size_t)(b * NSS + k - 1) * HD + hh];
        pref[(size_t)(b * NN + k) * HD + hh] = acc;
    }
}

// ---------------- vec @ mat (+bias) -----------------------------------------
__global__ void vecmat_kernel(const float* __restrict__ v, const float* __restrict__ Bm,
                              const float* __restrict__ bias, float* __restrict__ out,
                              int K, int N) {
    int n = blockIdx.x * blockDim.x + threadIdx.x;
    if (n >= N) return;
    float acc = bias ? bias[n] : 0.f;
    for (int k = 0; k < K; k++) acc += v[k] * Bm[(size_t)k * N + n];
    out[n] = acc;
}

// ---------------- layer-invariant logit term S2 -----------------------------
__global__ void s2_kernel(const float* __restrict__ prefS, const float* __restrict__ bs,
                          const float* __restrict__ W_d1, float* __restrict__ S2) {
    int bi = blockIdx.x;
    int b = bi / NN;
    int lane = threadIdx.x & 31, warp = threadIdx.x >> 5;
    const float* pi = prefS + (size_t)bi * HD;
    for (int j = warp; j < NN; j += 4) {
        const float* pj = prefS + (size_t)(b * NN + j) * HD;
        float acc = 0.f;
#pragma unroll
        for (int l = 0; l < 8; l++) {
            int hh = lane + l * 32;
            float v = pj[hh] - pi[hh] + bs[hh];
            acc += fmaxf(v, 0.f) * W_d1[HD + hh];
        }
        for (int o = 16; o; o >>= 1) acc += __shfl_xor_sync(0xFFFFFFFFu, acc, o);
        if (lane == 0) S2[(size_t)bi * NN + j] = acc;
    }
}

// ---------------- exec state init -------------------------------------------
__global__ void init_exec_kernel(const float* __restrict__ ia, const float* __restrict__ ib,
                                 float* __restrict__ c, float* __restrict__ h,
                                 float* __restrict__ p) {
    int idx = blockIdx.x * blockDim.x + threadIdx.x;
    if (idx < ROWS * HD) { c[idx] = ia[idx % HD]; h[idx] = ib[idx % HD]; }
    if (idx < ROWS) p[idx] = (idx % NN == 0) ? 1.f : 0.f;
}

// ---------------- per-layer: fused h_key matvec + masked softmax ------------
// mask[i,j] middle layers: (j > i && j <= len) || (j == len)
__global__ void hkey_softmax_kernel(const float* __restrict__ h, const float* __restrict__ W_hk,
                                    const float* __restrict__ b_hk, const float* __restrict__ W_d1,
                                    const float* __restrict__ S2, const float* __restrict__ b_d1,
                                    const float* __restrict__ p, const int* __restrict__ clen,
                                    int layer, float* __restrict__ w) {
    int bi = blockIdx.x, b = bi / NN, i = bi % NN;
    int tid = threadIdx.x;   // 256
    __shared__ float sh[HD];
    __shared__ float red[256];
    sh[tid] = h[(size_t)bi * HD + tid];
    __syncthreads();
    float acc = b_hk[tid];
#pragma unroll 8
    for (int k = 0; k < HD; k++) acc += sh[k] * W_hk[(size_t)k * HD + tid];
    red[tid] = fmaxf(acc, 0.f) * W_d1[tid];
    __syncthreads();
    for (int s = 128; s > 0; s >>= 1) {
        if (tid < s) red[tid] += red[tid + s];
        __syncthreads();
    }
    float a = red[0];
    __syncthreads();

    int len = clen[b] / TT;
    int j = tid;
    bool m = false;
    if (j < NN) {
        if (layer == 0)             m = (j == 1);
        else if (layer == NLAY - 1) m = (j == len);
        else                        m = ((j > i) && (j <= len)) || (j == len);
    }
    float logit = m ? (a + S2[(size_t)bi * NN + j] + b_d1[0]) : -1e30f;
    red[tid] = logit; __syncthreads();
    for (int s = 128; s > 0; s >>= 1) {
        if (tid < s) red[tid] = fmaxf(red[tid], red[tid + s]);
        __syncthreads();
    }
    float mx = red[0]; __syncthreads();
    float e = m ? __expf(logit - mx) : 0.f;
    red[tid] = e; __syncthreads();
    for (int s = 128; s > 0; s >>= 1) {
        if (tid < s) red[tid] += red[tid + s];
        __syncthreads();
    }
    float sum = red[0];
    if (j < NN) w[(size_t)bi * NN + j] = p[bi] * (e / sum);
}

// ---------------- per-layer: gated aggregation ------------------------------
// z[i,j] = pm4[j] + u[i]  where u = h@Wh_e + be - pm4 (per layer)
__global__ void agg_kernel(const float* __restrict__ w, const float* __restrict__ pm4,
                           const float* __restrict__ u,
                           const float* __restrict__ cIn, const float* __restrict__ hIn,
                           float* __restrict__ cOut, float* __restrict__ hOut,
                           float* __restrict__ pOut) {
    int bj = blockIdx.x, b = bj / NN, j = bj % NN;
    int hh = threadIdx.x;  // 256
    __shared__ float sw[NN];
    if (hh < NN) sw[hh] = w[((size_t)(b * NN + hh)) * NN + j];
    __syncthreads();
    const float* pj = pm4 + (size_t)bj * H4;
    float zj0 = pj[hh], zj1 = pj[HD + hh], zj2 = pj[2 * HD + hh], zj3 = pj[3 * HD + hh];
    float accC = 0.f, accH = 0.f, wsum = 0.f;
    for (int i = 0; i < NN; i++) {
        float wi = sw[i];
        wsum += wi;
        if (wi == 0.f) continue;
        int ri = b * NN + i;
        float cp, hp;
        if (j > i) {
            const float* ui = u + (size_t)ri * H4;
            float zi = zj0 + ui[hh];
            float zf = zj1 + ui[HD + hh];
            float zg = zj2 + ui[2 * HD + hh];
            float zo = zj3 + ui[3 * HD + hh];
            float cold = cIn[(size_t)ri * HD + hh];
            cp = sigf(zf) * cold + sigf(zi) * tanhr(zg);
            hp = sigf(zo) * tanhr(cp);
        } else {
            cp = cIn[(size_t)ri * HD + hh];
            hp = hIn[(size_t)ri * HD + hh];
        }
        accC += wi * cp;
        accH += wi * hp;
    }
    float denom = wsum + 1e-7f;
    cOut[(size_t)bj * HD + hh] = accC / denom;
    hOut[(size_t)bj * HD + hh] = accH / denom;
    if (hh == 0) pOut[bj] = wsum;
}

// ---------------------------------------------------------------------------
static float* sym(const void* s) {
    void* p = nullptr;
    cudaGetSymbolAddress(&p, s);
    return (float*)p;
}

extern "C" void kernel_launch(void* const* d_in, const int* in_sizes, int n_in,
                              void* d_out, int out_size) {
    const int*   ids    = (const int*)d_in[0];
    const int*   clen   = (const int*)d_in[1];
    const float* embed  = (const float*)d_in[2];
    const float* Wx_s   = (const float*)d_in[3];
    const float* Wh_s   = (const float*)d_in[4];
    const float* b_s    = (const float*)d_in[5];
    const float* W_se   = (const float*)d_in[6];
    const float* b_se   = (const float*)d_in[7];
    const float* Wx_e   = (const float*)d_in[8];
    const float* Wh_e   = (const float*)d_in[9];
    const float* b_e    = (const float*)d_in[10];
    const float* W_hk   = (const float*)d_in[11];
    const float* b_hk   = (const float*)d_in[12];
    const float* W_sd   = (const float*)d_in[13];
    const float* b_sd   = (const float*)d_in[14];
    const float* W_d1   = (const float*)d_in[15];
    const float* b_d1   = (const float*)d_in[16];
    const float* init_a = (const float*)d_in[17];
    const float* init_b = (const float*)d_in[18];

    float* xw   = sym(g_xw);
    float* Wt   = sym(g_Wt);
    float* c0   = sym(g_c0);
    float* hA   = sym(g_hA);
    float* hB   = sym(g_hB);
    float* pref = sym(g_pref);
    float* Me   = sym(g_Me);
    float* Ms   = sym(g_Ms);
    float* be   = sym(g_be);
    float* bs   = sym(g_bs);
    float* pm4  = sym(g_pm4);
    float* prS  = sym(g_prefS);
    float* S2   = sym(g_S2);
    float* uBuf = sym(g_u);
    float* wM   = sym(g_w);
    float* cX   = sym(g_cX);
    float* hX   = sym(g_hX);
    float* cY   = sym(g_cY);
    float* hY   = sym(g_hY);
    float* pX   = sym(g_pX);
    float* pY   = sym(g_pY);

    // 0) Wh_s -> gate-interleaved
    wt_kernel<<<(HD * H4 + 255) / 256, 256>>>(Wh_s, Wt);
    // 1) token projection: xw = embed[ids] @ Wx_s + b_s   [3072,1024]
    gemm_t<64, 128, 16, 4, 8><<<dim3(TOK / 64, H4 / 128), 256>>>(
        embed, ids, Wx_s, b_s, nullptr, 0, 0.f, xw, TOK, HD, H4);
    // 2) statement LSTM
    lstm_gate0_kernel<<<SEQS, 256>>>(xw, TT * H4, c0, hA);
    float *hs = hA, *hd = hB;
    for (int t = 1; t < TT; t++) {
        lstm_step_kernel<<<dim3(SEQS / 16, HD / 32), 256>>>(hs, Wt, xw + (size_t)t * H4, c0, hd);
        float* tmp = hs; hs = hd; hd = tmp;
    }
    // 3) prefix sums (final h in hs)
    cumsum_kernel<<<BB, HD>>>(hs, pref);
    // 4) composed weights/biases
    gemm_t<32, 64, 16, 2, 4><<<dim3(HD / 32, H4 / 64), 256>>>(
        W_se, nullptr, Wx_e, nullptr, nullptr, 0, 0.f, Me, HD, HD, H4);
    gemm_t<32, 64, 16, 2, 4><<<dim3(HD / 32, HD / 64), 256>>>(
        W_se, nullptr, W_sd, nullptr, nullptr, 0, 0.f, Ms, HD, HD, HD);
    vecmat_kernel<<<(H4 + 255) / 256, 256>>>(b_se, Wx_e, b_e, be, HD, H4);
    vecmat_kernel<<<1, 256>>>(b_se, W_sd, b_sd, bs, HD, HD);
    // 5) projected prefix tables
    gemm_t<32, 64, 16, 2, 4><<<dim3((ROWS + 31) / 32, H4 / 64), 256>>>(
        pref, nullptr, Me, nullptr, nullptr, 0, 0.f, pm4, ROWS, HD, H4);
    gemm_t<32, 64, 16, 2, 4><<<dim3((ROWS + 31) / 32, HD / 64), 256>>>(
        pref, nullptr, Ms, nullptr, nullptr, 0, 0.f, prS, ROWS, HD, HD);
    // 6) layer-invariant logit term
    s2_kernel<<<ROWS, 128>>>(prS, bs, W_d1, S2);
    // 7) execution state init
    init_exec_kernel<<<ROWS, 256>>>(init_a, init_b, cX, hX, pX);

    // 8) execution layers
    float *cS = cX, *hS = hX, *pS = pX, *cD = cY, *hD2 = hY, *pD = pY;
    for (int layer = 0; layer < NLAY; layer++) {
        // u = h @ Wh_e + be - pm4
        gemm_t<32, 64, 16, 2, 4><<<dim3((ROWS + 31) / 32, H4 / 64), 256>>>(
            hS, nullptr, Wh_e, be, pm4, H4, -1.f, uBuf, ROWS, HD, H4);
        hkey_softmax_kernel<<<ROWS, 256>>>(hS, W_hk, b_hk, W_d1, S2, b_d1,
                                           pS, clen, layer, wM);
        float* hOutPtr = (layer == NLAY - 1) ? (float*)d_out : hD2;
        agg_kernel<<<ROWS, 256>>>(wM, pm4, uBuf, cS, hS, cD, hOutPtr, pD);
        float* t;
        t = cS; cS = cD; cD = t;
        t = hS; hS = hD2; hD2 = t;
        t = pS; pS = pD; pD = t;
    }
}

// round 4
// speedup vs baseline: 1.1993x; 1.1993x over previous
#include <cuda_runtime.h>
#include <cstdio>

#define BB 4
#define NSS 96
#define TT 8
#define HD 256
#define H4 1024
#define NW 1280          // merged GEMM width (1024 + 256)
#define NN 97
#define NLAY 6
#define ROWS (BB*NN)     // 388
#define SEQS (BB*NSS)    // 384
#define TOK  (SEQS*TT)   // 3072
#define KS_L 8           // ksplit for lstm step
#define KS_U 4           // ksplit for layer/setup gemms

// ---------------- scratch (static device memory) ----------------------------
__device__ float g_xw[TOK*H4];         // token @ Wx_s + b_s
__device__ float g_Wt[HD*H4];          // Wh_s gate-interleaved [k][h*4+g]
__device__ float g_B1[HD*NW];          // [Wh_e | W_hk]
__device__ float g_B2[HD*NW];          // [Wx_e | W_sd]
__device__ float g_part8[KS_L*SEQS*H4];  // lstm partials (12.6MB)
__device__ float g_part4[KS_U*ROWS*NW];  // layer/setup partials (8MB)
__device__ float g_c0[SEQS*HD];
__device__ float g_hA[SEQS*HD];
__device__ float g_hB[SEQS*HD];
__device__ float g_pref[ROWS*HD];      // prefix sums
__device__ float g_MeMs[HD*NW];        // [W_se@Wx_e | W_se@W_sd]
__device__ float g_pmS[ROWS*NW];       // pref @ MeMs  (cols 0-1023 = pm4, 1024+ = prS)
__device__ float g_be[H4];             // b_se@Wx_e + b_e
__device__ float g_bs[HD];             // b_se@W_sd + b_sd
__device__ float g_S2[BB*NN*NN];
__device__ float g_u[ROWS*H4];         // h @ Wh_e + be - pm4
__device__ float g_w[BB*NN*NN];
__device__ float g_cX[ROWS*HD], g_hX[ROWS*HD];
__device__ float g_cY[ROWS*HD], g_hY[ROWS*HD];
__device__ float g_pX[ROWS], g_pY[ROWS];

__device__ __forceinline__ float sigf(float x)  { return 1.0f / (1.0f + __expf(-x)); }
__device__ __forceinline__ float tanhr(float x) { return 2.0f / (1.0f + __expf(-2.0f * x)) - 1.0f; }

// ---------------- full-K GEMM (token projection only) -----------------------
template<int BM, int BN, int BK, int TM, int TN>
__global__ void gemm_t(const float* __restrict__ A, const int* __restrict__ gidx,
                       const float* __restrict__ B, const float* __restrict__ bias,
                       float* __restrict__ C, int M, int K, int N) {
    constexpr int TX = BN / TN;
    static_assert((BM / TM) * TX == 256, "256 threads");
    __shared__ float sA[BK][BM + 4];
    __shared__ float sB[BK][BN];
    const int tid = threadIdx.x;
    const int tx = tid % TX, ty = tid / TX;
    const int bm = blockIdx.x * BM, bn = blockIdx.y * BN;
    float acc[TM][TN] = {};
    for (int k0 = 0; k0 < K; k0 += BK) {
        for (int l = tid; l < BM * BK / 4; l += 256) {
            int r = l / (BK / 4);
            int kc = (l % (BK / 4)) * 4;
            int row = bm + r;
            float4 v = make_float4(0.f, 0.f, 0.f, 0.f);
            if (row < M) {
                int ar = gidx ? gidx[row] : row;
                v = *(const float4*)(A + (size_t)ar * K + k0 + kc);
            }
            sA[kc + 0][r] = v.x; sA[kc + 1][r] = v.y;
            sA[kc + 2][r] = v.z; sA[kc + 3][r] = v.w;
        }
        for (int l = tid; l < BK * BN / 4; l += 256) {
            int kk = l / (BN / 4);
            int c = (l % (BN / 4)) * 4;
            *(float4*)(&sB[kk][c]) = *(const float4*)(B + (size_t)(k0 + kk) * N + bn + c);
        }
        __syncthreads();
#pragma unroll
        for (int kk = 0; kk < BK; kk++) {
            float a[TM], b[TN];
#pragma unroll
            for (int i = 0; i < TM; i++) a[i] = sA[kk][ty * TM + i];
#pragma unroll
            for (int j = 0; j < TN; j += 4) {
                float4 v = *(const float4*)(&sB[kk][tx * TN + j]);
                b[j] = v.x; b[j + 1] = v.y; b[j + 2] = v.z; b[j + 3] = v.w;
            }
#pragma unroll
            for (int i = 0; i < TM; i++)
#pragma unroll
                for (int j = 0; j < TN; j++)
                    acc[i][j] += a[i] * b[j];
        }
        __syncthreads();
    }
#pragma unroll
    for (int i = 0; i < TM; i++) {
        int row = bm + ty * TM + i;
        if (row >= M) continue;
#pragma unroll
        for (int j = 0; j < TN; j++) {
            int col = bn + tx * TN + j;
            C[(size_t)row * N + col] = acc[i][j] + (bias ? bias[col] : 0.f);
        }
    }
}

// ---------------- split-K partial GEMM: P[z] = A[:, zc:(z+1)c] @ B[zc:, :] --
template<int BM, int BN, int BK, int TM, int TN>
__global__ void gemm_part(const float* __restrict__ A, const float* __restrict__ B,
                          float* __restrict__ P, int M, int K, int N, int kchunk) {
    constexpr int TX = BN / TN;
    static_assert((BM / TM) * TX == 256, "256 threads");
    __shared__ float sA[BK][BM + 4];
    __shared__ float sB[BK][BN];
    const int tid = threadIdx.x;
    const int tx = tid % TX, ty = tid / TX;
    const int bm = blockIdx.x * BM, bn = blockIdx.y * BN;
    const int kbeg = blockIdx.z * kchunk, kend = kbeg + kchunk;
    float acc[TM][TN] = {};
    for (int k0 = kbeg; k0 < kend; k0 += BK) {
        for (int l = tid; l < BM * BK / 4; l += 256) {
            int r = l / (BK / 4);
            int kc = (l % (BK / 4)) * 4;
            int row = bm + r;
            float4 v = make_float4(0.f, 0.f, 0.f, 0.f);
            if (row < M) v = *(const float4*)(A + (size_t)row * K + k0 + kc);
            sA[kc + 0][r] = v.x; sA[kc + 1][r] = v.y;
            sA[kc + 2][r] = v.z; sA[kc + 3][r] = v.w;
        }
        for (int l = tid; l < BK * BN / 4; l += 256) {
            int kk = l / (BN / 4);
            int c = (l % (BN / 4)) * 4;
            *(float4*)(&sB[kk][c]) = *(const float4*)(B + (size_t)(k0 + kk) * N + bn + c);
        }
        __syncthreads();
#pragma unroll
        for (int kk = 0; kk < BK; kk++) {
            float a[TM], b[TN];
#pragma unroll
            for (int i = 0; i < TM; i++) a[i] = sA[kk][ty * TM + i];
#pragma unroll
            for (int j = 0; j < TN; j += 4) {
                float4 v = *(const float4*)(&sB[kk][tx * TN + j]);
                b[j] = v.x; b[j + 1] = v.y; b[j + 2] = v.z; b[j + 3] = v.w;
            }
#pragma unroll
            for (int i = 0; i < TM; i++)
#pragma unroll
                for (int j = 0; j < TN; j++)
                    acc[i][j] += a[i] * b[j];
        }
        __syncthreads();
    }
    float* Pz = P + (size_t)blockIdx.z * M * N;
#pragma unroll
    for (int i = 0; i < TM; i++) {
        int row = bm + ty * TM + i;
        if (row >= M) continue;
#pragma unroll
        for (int j = 0; j < TN; j++)
            Pz[(size_t)row * N + bn + tx * TN + j] = acc[i][j];
    }
}

// ---------------- small helpers ---------------------------------------------
__global__ void wt_kernel(const float* __restrict__ Wh, float* __restrict__ Wt) {
    int idx = blockIdx.x * 256 + threadIdx.x;
    if (idx >= HD * H4) return;
    int k = idx / H4, col = idx % H4;
    int g = col / HD, hh = col % HD;
    Wt[(size_t)k * H4 + hh * 4 + g] = Wh[idx];
}

// dst[256][1280] = [src1 (1024 cols) | src2 (256 cols)]
__global__ void copyB_kernel(const float* __restrict__ s1, const float* __restrict__ s2,
                             float* __restrict__ dst) {
    int idx = blockIdx.x * 256 + threadIdx.x;
    if (idx >= HD * NW) return;
    int k = idx / NW, c = idx % NW;
    dst[idx] = (c < H4) ? s1[(size_t)k * H4 + c] : s2[(size_t)k * HD + (c - H4)];
}

__global__ void sum4_kernel(const float* __restrict__ P, float* __restrict__ out,
                            int n, int stride) {
    int idx = blockIdx.x * 256 + threadIdx.x;
    if (idx >= n) return;
    out[idx] = P[idx] + P[idx + stride] + P[idx + 2 * stride] + P[idx + 3 * stride];
}

// ---------------- statement LSTM --------------------------------------------
__global__ void lstm_gate0_kernel(const float* __restrict__ z, float* __restrict__ c,
                                  float* __restrict__ h) {
    int idx = blockIdx.x * blockDim.x + threadIdx.x;
    if (idx >= SEQS * HD) return;
    int s = idx / HD, hh = idx % HD;
    const float* zr = z + (size_t)s * (TT * H4);
    float zi = zr[hh], zg = zr[2 * HD + hh], zo = zr[3 * HD + hh];
    float c2 = sigf(zi) * tanhr(zg);
    h[idx] = sigf(zo) * tanhr(c2);
    c[idx] = c2;
}

// sum 8 gate-interleaved partials + xw, apply gates
__global__ void lstm_combine_kernel(const float* __restrict__ P, const float* __restrict__ xw_t,
                                    float* __restrict__ c_st, float* __restrict__ hout) {
    int idx = blockIdx.x * blockDim.x + threadIdx.x;
    if (idx >= SEQS * HD) return;
    int row = idx / HD, hh = idx % HD;
    float4 z4 = make_float4(0.f, 0.f, 0.f, 0.f);
    size_t off = (size_t)row * H4 + hh * 4;
#pragma unroll
    for (int s = 0; s < KS_L; s++) {
        float4 v = *(const float4*)(P + (size_t)s * SEQS * H4 + off);
        z4.x += v.x; z4.y += v.y; z4.z += v.z; z4.w += v.w;
    }
    const float* xr = xw_t + (size_t)row * (TT * H4);
    float zi = z4.x + xr[hh];
    float zf = z4.y + xr[HD + hh];
    float zg = z4.z + xr[2 * HD + hh];
    float zo = z4.w + xr[3 * HD + hh];
    float cp = c_st[idx];
    float c2 = sigf(zf) * cp + sigf(zi) * tanhr(zg);
    c_st[idx] = c2;
    hout[idx] = sigf(zo) * tanhr(c2);
}

// ---------------- prefix sums -----------------------------------------------
__global__ void cumsum_kernel(const float* __restrict__ stmt, float* __restrict__ pref) {
    int b = blockIdx.x, hh = threadIdx.x;
    float acc = 0.f;
    pref[(size_t)(b * NN) * HD + hh] = 0.f;
    for (int k = 1; k < NN; k++) {
        acc += stmt[(size_t)(b * NSS + k - 1) * HD + hh];
        pref[(size_t)(b * NN + k) * HD + hh] = acc;
    }
}

__global__ void vecmat_kernel(const float* __restrict__ v, const float* __restrict__ Bm,
                              const float* __restrict__ bias, float* __restrict__ out,
                              int K, int N) {
    int n = blockIdx.x * blockDim.x + threadIdx.x;
    if (n >= N) return;
    float acc = bias ? bias[n] : 0.f;
    for (int k = 0; k < K; k++) acc += v[k] * Bm[(size_t)k * N + n];
    out[n] = acc;
}

// ---------------- layer-invariant logit term S2 (prS = pmS cols 1024+) ------
__global__ void s2_kernel(const float* __restrict__ pmS, const float* __restrict__ bs,
                          const float* __restrict__ W_d1, float* __restrict__ S2) {
    int bi = blockIdx.x;
    int b = bi / NN;
    int lane = threadIdx.x & 31, warp = threadIdx.x >> 5;
    const float* pi = pmS + (size_t)bi * NW + H4;
    for (int j = warp; j < NN; j += 4) {
        const float* pj = pmS + (size_t)(b * NN + j) * NW + H4;
        float acc = 0.f;
#pragma unroll
        for (int l = 0; l < 8; l++) {
            int hh = lane + l * 32;
            float v = pj[hh] - pi[hh] + bs[hh];
            acc += fmaxf(v, 0.f) * W_d1[HD + hh];
        }
        for (int o = 16; o; o >>= 1) acc += __shfl_xor_sync(0xFFFFFFFFu, acc, o);
        if (lane == 0) S2[(size_t)bi * NN + j] = acc;
    }
}

__global__ void init_exec_kernel(const float* __restrict__ ia, const float* __restrict__ ib,
                                 float* __restrict__ c, float* __restrict__ h,
                                 float* __restrict__ p) {
    int idx = blockIdx.x * blockDim.x + threadIdx.x;
    if (idx < ROWS * HD) { c[idx] = ia[idx % HD]; h[idx] = ib[idx % HD]; }
    if (idx < ROWS) p[idx] = (idx % NN == 0) ? 1.f : 0.f;
}

// ---------------- u combine: u = sum4(partU[:, :1024]) + be - pm4 -----------
__global__ void u_combine_kernel(const float* __restrict__ P, const float* __restrict__ be,
                                 const float* __restrict__ pmS, float* __restrict__ u) {
    int idx = blockIdx.x * 256 + threadIdx.x;
    if (idx >= ROWS * H4) return;
    int row = idx / H4, c = idx % H4;
    size_t off = (size_t)row * NW + c;
    float v = P[off] + P[off + (size_t)ROWS * NW] + P[off + 2 * (size_t)ROWS * NW]
            + P[off + 3 * (size_t)ROWS * NW];
    u[idx] = v + be[c] - pmS[off];
}

// ---------------- per-layer: hkey reduce (from partials) + masked softmax ---
__global__ void softmax_kernel(const float* __restrict__ P, const float* __restrict__ b_hk,
                               const float* __restrict__ W_d1,
                               const float* __restrict__ S2, const float* __restrict__ b_d1,
                               const float* __restrict__ p, const int* __restrict__ clen,
                               int layer, float* __restrict__ w) {
    int bi = blockIdx.x, b = bi / NN, i = bi % NN;
    int tid = threadIdx.x;   // 256
    __shared__ float red[256];
    // hk[tid] = sum of 4 partials at col 1024+tid
    size_t off = (size_t)bi * NW + H4 + tid;
    float hk = P[off] + P[off + (size_t)ROWS * NW] + P[off + 2 * (size_t)ROWS * NW]
             + P[off + 3 * (size_t)ROWS * NW] + b_hk[tid];
    red[tid] = fmaxf(hk, 0.f) * W_d1[tid];
    __syncthreads();
    for (int s = 128; s > 0; s >>= 1) {
        if (tid < s) red[tid] += red[tid + s];
        __syncthreads();
    }
    float a = red[0];
    __syncthreads();

    int len = clen[b] / TT;
    int j = tid;
    bool m = false;
    if (j < NN) {
        if (layer == 0)             m = (j == 1);
        else if (layer == NLAY - 1) m = (j == len);
        else                        m = ((j > i) && (j <= len)) || (j == len);
    }
    float logit = m ? (a + S2[(size_t)bi * NN + j] + b_d1[0]) : -1e30f;
    red[tid] = logit; __syncthreads();
    for (int s = 128; s > 0; s >>= 1) {
        if (tid < s) red[tid] = fmaxf(red[tid], red[tid + s]);
        __syncthreads();
    }
    float mx = red[0]; __syncthreads();
    float e = m ? __expf(logit - mx) : 0.f;
    red[tid] = e; __syncthreads();
    for (int s = 128; s > 0; s >>= 1) {
        if (tid < s) red[tid] += red[tid + s];
        __syncthreads();
    }
    float sum = red[0];
    if (j < NN) w[(size_t)bi * NN + j] = p[bi] * (e / sum);
}

// ---------------- per-layer: gated aggregation ------------------------------
__global__ void agg_kernel(const float* __restrict__ w, const float* __restrict__ pmS,
                           const float* __restrict__ u,
                           const float* __restrict__ cIn, const float* __restrict__ hIn,
                           float* __restrict__ cOut, float* __restrict__ hOut,
                           float* __restrict__ pOut) {
    int bj = blockIdx.x, b = bj / NN, j = bj % NN;
    int hh = threadIdx.x;  // 256
    __shared__ float sw[NN];
    if (hh < NN) sw[hh] = w[((size_t)(b * NN + hh)) * NN + j];
    __syncthreads();
    const float* pj = pmS + (size_t)bj * NW;
    float zj0 = pj[hh], zj1 = pj[HD + hh], zj2 = pj[2 * HD + hh], zj3 = pj[3 * HD + hh];
    float accC = 0.f, accH = 0.f, wsum = 0.f;
    for (int i = 0; i < NN; i++) {
        float wi = sw[i];
        wsum += wi;
        if (wi == 0.f) continue;
        int ri = b * NN + i;
        float cp, hp;
        if (j > i) {
            const float* ui = u + (size_t)ri * H4;
            float zi = zj0 + ui[hh];
            float zf = zj1 + ui[HD + hh];
            float zg = zj2 + ui[2 * HD + hh];
            float zo = zj3 + ui[3 * HD + hh];
            float cold = cIn[(size_t)ri * HD + hh];
            cp = sigf(zf) * cold + sigf(zi) * tanhr(zg);
            hp = sigf(zo) * tanhr(cp);
        } else {
            cp = cIn[(size_t)ri * HD + hh];
            hp = hIn[(size_t)ri * HD + hh];
        }
        accC += wi * cp;
        accH += wi * hp;
    }
    float denom = wsum + 1e-7f;
    cOut[(size_t)bj * HD + hh] = accC / denom;
    hOut[(size_t)bj * HD + hh] = accH / denom;
    if (hh == 0) pOut[bj] = wsum;
}

// ---------------------------------------------------------------------------
static float* sym(const void* s) {
    void* p = nullptr;
    cudaGetSymbolAddress(&p, s);
    return (float*)p;
}

extern "C" void kernel_launch(void* const* d_in, const int* in_sizes, int n_in,
                              void* d_out, int out_size) {
    const int*   ids    = (const int*)d_in[0];
    const int*   clen   = (const int*)d_in[1];
    const float* embed  = (const float*)d_in[2];
    const float* Wx_s   = (const float*)d_in[3];
    const float* Wh_s   = (const float*)d_in[4];
    const float* b_s    = (const float*)d_in[5];
    const float* W_se   = (const float*)d_in[6];
    const float* b_se   = (const float*)d_in[7];
    const float* Wx_e   = (const float*)d_in[8];
    const float* Wh_e   = (const float*)d_in[9];
    const float* b_e    = (const float*)d_in[10];
    const float* W_hk   = (const float*)d_in[11];
    const float* b_hk   = (const float*)d_in[12];
    const float* W_sd   = (const float*)d_in[13];
    const float* b_sd   = (const float*)d_in[14];
    const float* W_d1   = (const float*)d_in[15];
    const float* b_d1   = (const float*)d_in[16];
    const float* init_a = (const float*)d_in[17];
    const float* init_b = (const float*)d_in[18];

    float* xw    = sym(g_xw);
    float* Wt    = sym(g_Wt);
    float* B1    = sym(g_B1);
    float* B2    = sym(g_B2);
    float* part8 = sym(g_part8);
    float* part4 = sym(g_part4);
    float* c0    = sym(g_c0);
    float* hA    = sym(g_hA);
    float* hB    = sym(g_hB);
    float* pref  = sym(g_pref);
    float* MeMs  = sym(g_MeMs);
    float* pmS   = sym(g_pmS);
    float* be    = sym(g_be);
    float* bs    = sym(g_bs);
    float* S2    = sym(g_S2);
    float* uBuf  = sym(g_u);
    float* wM    = sym(g_w);
    float* cX    = sym(g_cX);
    float* hX    = sym(g_hX);
    float* cY    = sym(g_cY);
    float* hY    = sym(g_hY);
    float* pX    = sym(g_pX);
    float* pY    = sym(g_pY);

    // 0) weight reshapes / merges
    wt_kernel<<<(HD * H4 + 255) / 256, 256>>>(Wh_s, Wt);
    copyB_kernel<<<(HD * NW + 255) / 256, 256>>>(Wh_e, W_hk, B1);
    copyB_kernel<<<(HD * NW + 255) / 256, 256>>>(Wx_e, W_sd, B2);

    // 1) token projection: xw = embed[ids] @ Wx_s + b_s
    gemm_t<64, 128, 16, 4, 8><<<dim3(TOK / 64, H4 / 128), 256>>>(
        embed, ids, Wx_s, b_s, xw, TOK, HD, H4);

    // 2) statement LSTM (split-K recurrent steps)
    lstm_gate0_kernel<<<(SEQS * HD + 255) / 256, 256>>>(xw, c0, hA);
    float *hs = hA, *hd = hB;
    for (int t = 1; t < TT; t++) {
        gemm_part<64, 128, 16, 4, 8><<<dim3(SEQS / 64, H4 / 128, KS_L), 256>>>(
            hs, Wt, part8, SEQS, HD, H4, HD / KS_L);
        lstm_combine_kernel<<<(SEQS * HD + 255) / 256, 256>>>(
            part8, xw + (size_t)t * H4, c0, hd);
        float* tmp = hs; hs = hd; hd = tmp;
    }

    // 3) prefix sums
    cumsum_kernel<<<BB, HD>>>(hs, pref);

    // 4) composed tables: MeMs = W_se @ [Wx_e|W_sd];  pmS = pref @ MeMs
    gemm_part<64, 128, 16, 4, 8><<<dim3(HD / 64, NW / 128, KS_U), 256>>>(
        W_se, B2, part4, HD, HD, NW, HD / KS_U);
    sum4_kernel<<<(HD * NW + 255) / 256, 256>>>(part4, MeMs, HD * NW, HD * NW);
    gemm_part<64, 128, 16, 4, 8><<<dim3((ROWS + 63) / 64, NW / 128, KS_U), 256>>>(
        pref, MeMs, part4, ROWS, HD, NW, HD / KS_U);
    sum4_kernel<<<(ROWS * NW + 255) / 256, 256>>>(part4, pmS, ROWS * NW, ROWS * NW);
    vecmat_kernel<<<(H4 + 255) / 256, 256>>>(b_se, Wx_e, b_e, be, HD, H4);
    vecmat_kernel<<<1, 256>>>(b_se, W_sd, b_sd, bs, HD, HD);

    // 5) layer-invariant logit term + exec init
    s2_kernel<<<ROWS, 128>>>(pmS, bs, W_d1, S2);
    init_exec_kernel<<<ROWS, 256>>>(init_a, init_b, cX, hX, pX);

    // 6) execution layers
    float *cS = cX, *hS = hX, *pS = pX, *cD = cY, *hD2 = hY, *pD = pY;
    for (int layer = 0; layer < NLAY; layer++) {
        // partials of hS @ [Wh_e | W_hk]
        gemm_part<64, 128, 16, 4, 8><<<dim3((ROWS + 63) / 64, NW / 128, KS_U), 256>>>(
            hS, B1, part4, ROWS, HD, NW, HD / KS_U);
        u_combine_kernel<<<(ROWS * H4 + 255) / 256, 256>>>(part4, be, pmS, uBuf);
        softmax_kernel<<<ROWS, 256>>>(part4, b_hk, W_d1, S2, b_d1, pS, clen, layer, wM);
        float* hOutPtr = (layer == NLAY - 1) ? (float*)d_out : hD2;
        agg_kernel<<<ROWS, 256>>>(wM, pmS, uBuf, cS, hS, cD, hOutPtr, pD);
        float* t;
        t = cS; cS = cD; cD = t;
        t = hS; hS = hD2; hD2 = t;
        t = pS; pS = pD; pD = t;
    }
}

// round 5
// speedup vs baseline: 1.6097x; 1.3422x over previous
#include <cuda_runtime.h>
#include <cstdio>
#include <cstdint>

#define BB 4
#define NSS 96
#define TT 8
#define HD 256
#define H4 1024
#define NW 1280
#define NN 97
#define NLAY 6
#define ROWS (BB*NN)     // 388
#define SEQS (BB*NSS)    // 384
#define TOK  (SEQS*TT)   // 3072

// ---------------- scratch -----------------------------------------------------
__device__ float g_xw[TOK*H4];
__device__ float g_Wt[HD*H4];          // Wh_s gate-interleaved [k][h*4+g]
__device__ float g_B1[HD*NW];          // [Wh_e | W_hk]
__device__ float g_B2[HD*NW];          // [Wx_e | W_sd]
__device__ float g_c0[SEQS*HD];
__device__ float g_hA[SEQS*HD];
__device__ float g_hB[SEQS*HD];
__device__ float g_pref[ROWS*HD];
__device__ float g_MeMs[HD*NW];
__device__ float g_pmS[ROWS*NW];       // cols 0-1023 = pm4, 1024+ = prS
__device__ float g_be[H4];
__device__ float g_bs[HD];
__device__ float g_S2[BB*NN*NN];
__device__ float g_u[ROWS*H4];
__device__ float g_hk[ROWS*HD];        // relu(h@W_hk + b_hk) * W_d1[:256]
__device__ float g_w[BB*NN*NN];
__device__ float g_cX[ROWS*HD], g_hX[ROWS*HD];
__device__ float g_cY[ROWS*HD], g_hY[ROWS*HD];
__device__ float g_pX[ROWS], g_pY[ROWS];

__device__ __forceinline__ float sigf(float x)  { return 1.0f / (1.0f + __expf(-x)); }
__device__ __forceinline__ float tanhr(float x) { return 2.0f / (1.0f + __expf(-2.0f * x)) - 1.0f; }

__device__ __forceinline__ float to_tf32(float x) {
    uint32_t o;
    asm("cvt.rna.tf32.f32 %0, %1;" : "=r"(o) : "f"(x));
    return __uint_as_float(o);
}

__device__ __forceinline__ void mma_tf32(float& c0, float& c1, float& c2, float& c3,
                                         float a0, float a1, float a2, float a3,
                                         float b0, float b1) {
    asm volatile(
        "mma.sync.aligned.m16n8k8.row.col.f32.tf32.tf32.f32 "
        "{%0,%1,%2,%3},{%4,%5,%6,%7},{%8,%9},{%0,%1,%2,%3};"
        : "+f"(c0), "+f"(c1), "+f"(c2), "+f"(c3)
        : "r"(__float_as_uint(a0)), "r"(__float_as_uint(a1)),
          "r"(__float_as_uint(a2)), "r"(__float_as_uint(a3)),
          "r"(__float_as_uint(b0)), "r"(__float_as_uint(b1)));
}

// ---------------- tf32 MMA GEMM, K=256, tile 64x64, 256 threads ---------------
// EPI: 0 = plain (+opt bias), 1 = LSTM gates fused, 2 = layer (u + hk)
#define SA_STRIDE 36
#define SB_STRIDE 72
#define BUF_STRIDE 68
template<int EPI>
__global__ __launch_bounds__(256)
void mma_gemm(const float* __restrict__ A, const int* __restrict__ gidx,
              const float* __restrict__ B, const float* __restrict__ bias,
              float* __restrict__ C, int M, int N,
              const float* __restrict__ xw_t, float* __restrict__ c_st,
              float* __restrict__ hout,
              const float* __restrict__ be, const float* __restrict__ pmS,
              const float* __restrict__ b_hk, const float* __restrict__ W_d1,
              float* __restrict__ u, float* __restrict__ hkbuf) {
    __shared__ float smem[64 * SA_STRIDE + 32 * SB_STRIDE];   // 4608 floats
    float* sA = smem;                       // [64][36]  (m,k)
    float* sB = smem + 64 * SA_STRIDE;      // [32][72]  (k,n)
    const int tid = threadIdx.x;
    const int lane = tid & 31, warp = tid >> 5;
    const int wm = warp >> 1, wn = warp & 1;     // 4x2 warp grid
    const int g = lane >> 2, tg = lane & 3;
    const int bm = blockIdx.x * 64, bn = blockIdx.y * 64;
    const int K = HD;

    float acc[4][4];
#pragma unroll
    for (int a = 0; a < 4; a++)
#pragma unroll
        for (int b = 0; b < 4; b++) acc[a][b] = 0.f;

    for (int k0 = 0; k0 < K; k0 += 32) {
        // A tile: 64 rows x 32 k -> 512 float4, 2 per thread
#pragma unroll
        for (int l = 0; l < 2; l++) {
            int t = tid + l * 256;
            int r = t >> 3;
            int kc = (t & 7) << 2;
            int row = bm + r;
            float4 v = make_float4(0.f, 0.f, 0.f, 0.f);
            if (row < M) {
                int ar = gidx ? gidx[row] : row;
                v = *(const float4*)(A + (size_t)ar * K + k0 + kc);
            }
            float* d = sA + r * SA_STRIDE + kc;
            d[0] = to_tf32(v.x); d[1] = to_tf32(v.y);
            d[2] = to_tf32(v.z); d[3] = to_tf32(v.w);
        }
        // B tile: 32 k x 64 n -> 512 float4
#pragma unroll
        for (int l = 0; l < 2; l++) {
            int t = tid + l * 256;
            int kk = t >> 4;
            int c = (t & 15) << 2;
            float4 v = *(const float4*)(B + (size_t)(k0 + kk) * N + bn + c);
            float* d = sB + kk * SB_STRIDE + c;
            d[0] = to_tf32(v.x); d[1] = to_tf32(v.y);
            d[2] = to_tf32(v.z); d[3] = to_tf32(v.w);
        }
        __syncthreads();
#pragma unroll
        for (int k8 = 0; k8 < 4; k8++) {
            int kb = k8 * 8;
            float a0 = sA[(wm * 16 + g) * SA_STRIDE + kb + tg];
            float a1 = sA[(wm * 16 + g + 8) * SA_STRIDE + kb + tg];
            float a2 = sA[(wm * 16 + g) * SA_STRIDE + kb + tg + 4];
            float a3 = sA[(wm * 16 + g + 8) * SA_STRIDE + kb + tg + 4];
#pragma unroll
            for (int nt = 0; nt < 4; nt++) {
                int nc = wn * 32 + nt * 8 + g;
                float b0 = sB[(kb + tg) * SB_STRIDE + nc];
                float b1 = sB[(kb + tg + 4) * SB_STRIDE + nc];
                mma_tf32(acc[nt][0], acc[nt][1], acc[nt][2], acc[nt][3],
                         a0, a1, a2, a3, b0, b1);
            }
        }
        __syncthreads();
    }

    if (EPI == 1) {
        // stage to smem buf [64][68], regroup gates, apply LSTM
        float* buf = smem;
#pragma unroll
        for (int nt = 0; nt < 4; nt++)
#pragma unroll
            for (int e = 0; e < 4; e++) {
                int lr = wm * 16 + g + ((e >> 1) ? 8 : 0);
                int lc = wn * 32 + nt * 8 + tg * 2 + (e & 1);
                buf[lr * BUF_STRIDE + lc] = acc[nt][e];
            }
        __syncthreads();
#pragma unroll
        for (int l = 0; l < 4; l++) {
            int pi = tid + l * 256;          // 1024 = 64 rows x 16 hidden
            int lr = pi & 63;
            int lh = pi >> 6;                // 0..15
            int row = bm + lr;
            int hh = (bn >> 2) + lh;         // global hidden unit
            float4 z4 = *(const float4*)(buf + lr * BUF_STRIDE + lh * 4);
            const float* xr = xw_t + (size_t)row * (TT * H4);
            float zi = z4.x + xr[hh];
            float zf = z4.y + xr[HD + hh];
            float zg = z4.z + xr[2 * HD + hh];
            float zo = z4.w + xr[3 * HD + hh];
            size_t idx = (size_t)row * HD + hh;
            float cp = c_st[idx];
            float c2 = sigf(zf) * cp + sigf(zi) * tanhr(zg);
            c_st[idx] = c2;
            hout[idx] = sigf(zo) * tanhr(c2);
        }
        return;
    }

#pragma unroll
    for (int nt = 0; nt < 4; nt++)
#pragma unroll
        for (int e = 0; e < 4; e++) {
            int row = bm + wm * 16 + g + ((e >> 1) ? 8 : 0);
            int col = bn + wn * 32 + nt * 8 + tg * 2 + (e & 1);
            if (row >= M) continue;
            float v = acc[nt][e];
            if (EPI == 0) {
                C[(size_t)row * N + col] = v + (bias ? bias[col] : 0.f);
            } else {  // EPI == 2
                if (col < H4) {
                    u[(size_t)row * H4 + col] = v + be[col] - pmS[(size_t)row * NW + col];
                } else {
                    int cc = col - H4;
                    hkbuf[(size_t)row * HD + cc] =
                        fmaxf(v + b_hk[cc], 0.f) * W_d1[cc];
                }
            }
        }
}

// ---------------- small helpers -----------------------------------------------
__global__ void wt_kernel(const float* __restrict__ Wh, float* __restrict__ Wt) {
    int idx = blockIdx.x * 256 + threadIdx.x;
    if (idx >= HD * H4) return;
    int k = idx / H4, col = idx % H4;
    int g = col / HD, hh = col % HD;
    Wt[(size_t)k * H4 + hh * 4 + g] = Wh[idx];
}

__global__ void copyB_kernel(const float* __restrict__ s1, const float* __restrict__ s2,
                             float* __restrict__ dst) {
    int idx = blockIdx.x * 256 + threadIdx.x;
    if (idx >= HD * NW) return;
    int k = idx / NW, c = idx % NW;
    dst[idx] = (c < H4) ? s1[(size_t)k * H4 + c] : s2[(size_t)k * HD + (c - H4)];
}

__global__ void lstm_gate0_kernel(const float* __restrict__ z, float* __restrict__ c,
                                  float* __restrict__ h) {
    int idx = blockIdx.x * blockDim.x + threadIdx.x;
    if (idx >= SEQS * HD) return;
    int s = idx / HD, hh = idx % HD;
    const float* zr = z + (size_t)s * (TT * H4);
    float zi = zr[hh], zg = zr[2 * HD + hh], zo = zr[3 * HD + hh];
    float c2 = sigf(zi) * tanhr(zg);
    h[idx] = sigf(zo) * tanhr(c2);
    c[idx] = c2;
}

__global__ void cumsum_kernel(const float* __restrict__ stmt, float* __restrict__ pref) {
    int b = blockIdx.x, hh = threadIdx.x;
    float acc = 0.f;
    pref[(size_t)(b * NN) * HD + hh] = 0.f;
    for (int k = 1; k < NN; k++) {
        acc += stmt[(size_t)(b * NSS + k - 1) * HD + hh];
        pref[(size_t)(b * NN + k) * HD + hh] = acc;
    }
}

__global__ void vecmat_kernel(const float* __restrict__ v, const float* __restrict__ Bm,
                              const float* __restrict__ bias, float* __restrict__ out,
                              int K, int N) {
    int n = blockIdx.x * blockDim.x + threadIdx.x;
    if (n >= N) return;
    float acc = bias ? bias[n] : 0.f;
    for (int k = 0; k < K; k++) acc += v[k] * Bm[(size_t)k * N + n];
    out[n] = acc;
}

__global__ void s2_kernel(const float* __restrict__ pmS, const float* __restrict__ bs,
                          const float* __restrict__ W_d1, float* __restrict__ S2) {
    int bi = blockIdx.x;
    int b = bi / NN;
    int lane = threadIdx.x & 31, warp = threadIdx.x >> 5;
    const float* pi = pmS + (size_t)bi * NW + H4;
    for (int j = warp; j < NN; j += 4) {
        const float* pj = pmS + (size_t)(b * NN + j) * NW + H4;
        float acc = 0.f;
#pragma unroll
        for (int l = 0; l < 8; l++) {
            int hh = lane + l * 32;
            float v = pj[hh] - pi[hh] + bs[hh];
            acc += fmaxf(v, 0.f) * W_d1[HD + hh];
        }
        for (int o = 16; o; o >>= 1) acc += __shfl_xor_sync(0xFFFFFFFFu, acc, o);
        if (lane == 0) S2[(size_t)bi * NN + j] = acc;
    }
}

__global__ void init_exec_kernel(const float* __restrict__ ia, const float* __restrict__ ib,
                                 float* __restrict__ c, float* __restrict__ h,
                                 float* __restrict__ p) {
    int idx = blockIdx.x * blockDim.x + threadIdx.x;
    if (idx < ROWS * HD) { c[idx] = ia[idx % HD]; h[idx] = ib[idx % HD]; }
    if (idx < ROWS) p[idx] = (idx % NN == 0) ? 1.f : 0.f;
}

// ---------------- per-layer: softmax (hk already reduced per element) ---------
__global__ void softmax_kernel(const float* __restrict__ hkbuf,
                               const float* __restrict__ S2, const float* __restrict__ b_d1,
                               const float* __restrict__ p, const int* __restrict__ clen,
                               int layer, float* __restrict__ w) {
    int bi = blockIdx.x, b = bi / NN, i = bi % NN;
    int tid = threadIdx.x;   // 256
    __shared__ float red[256];
    red[tid] = hkbuf[(size_t)bi * HD + tid];
    __syncthreads();
    for (int s = 128; s > 0; s >>= 1) {
        if (tid < s) red[tid] += red[tid + s];
        __syncthreads();
    }
    float a = red[0];
    __syncthreads();

    int len = clen[b] / TT;
    int j = tid;
    bool m = false;
    if (j < NN) {
        if (layer == 0)             m = (j == 1);
        else if (layer == NLAY - 1) m = (j == len);
        else                        m = ((j > i) && (j <= len)) || (j == len);
    }
    float logit = m ? (a + S2[(size_t)bi * NN + j] + b_d1[0]) : -1e30f;
    red[tid] = logit; __syncthreads();
    for (int s = 128; s > 0; s >>= 1) {
        if (tid < s) red[tid] = fmaxf(red[tid], red[tid + s]);
        __syncthreads();
    }
    float mx = red[0]; __syncthreads();
    float e = m ? __expf(logit - mx) : 0.f;
    red[tid] = e; __syncthreads();
    for (int s = 128; s > 0; s >>= 1) {
        if (tid < s) red[tid] += red[tid + s];
        __syncthreads();
    }
    float sum = red[0];
    if (j < NN) w[(size_t)bi * NN + j] = p[bi] * (e / sum);
}

// ---------------- per-layer: gated aggregation --------------------------------
__global__ void agg_kernel(const float* __restrict__ w, const float* __restrict__ pmS,
                           const float* __restrict__ u,
                           const float* __restrict__ cIn, const float* __restrict__ hIn,
                           float* __restrict__ cOut, float* __restrict__ hOut,
                           float* __restrict__ pOut) {
    int bj = blockIdx.x, b = bj / NN, j = bj % NN;
    int hh = threadIdx.x;  // 256
    __shared__ float sw[NN];
    if (hh < NN) sw[hh] = w[((size_t)(b * NN + hh)) * NN + j];
    __syncthreads();
    const float* pj = pmS + (size_t)bj * NW;
    float zj0 = pj[hh], zj1 = pj[HD + hh], zj2 = pj[2 * HD + hh], zj3 = pj[3 * HD + hh];
    float accC = 0.f, accH = 0.f, wsum = 0.f;
    for (int i = 0; i < NN; i++) {
        float wi = sw[i];
        wsum += wi;
        if (wi == 0.f) continue;
        int ri = b * NN + i;
        float cp, hp;
        if (j > i) {
            const float* ui = u + (size_t)ri * H4;
            float zi = zj0 + ui[hh];
            float zf = zj1 + ui[HD + hh];
            float zg = zj2 + ui[2 * HD + hh];
            float zo = zj3 + ui[3 * HD + hh];
            float cold = cIn[(size_t)ri * HD + hh];
            cp = sigf(zf) * cold + sigf(zi) * tanhr(zg);
            hp = sigf(zo) * tanhr(cp);
        } else {
            cp = cIn[(size_t)ri * HD + hh];
            hp = hIn[(size_t)ri * HD + hh];
        }
        accC += wi * cp;
        accH += wi * hp;
    }
    float denom = wsum + 1e-7f;
    cOut[(size_t)bj * HD + hh] = accC / denom;
    hOut[(size_t)bj * HD + hh] = accH / denom;
    if (hh == 0) pOut[bj] = wsum;
}

// ------------------------------------------------------------------------------
static float* sym(const void* s) {
    void* p = nullptr;
    cudaGetSymbolAddress(&p, s);
    return (float*)p;
}

extern "C" void kernel_launch(void* const* d_in, const int* in_sizes, int n_in,
                              void* d_out, int out_size) {
    const int*   ids    = (const int*)d_in[0];
    const int*   clen   = (const int*)d_in[1];
    const float* embed  = (const float*)d_in[2];
    const float* Wx_s   = (const float*)d_in[3];
    const float* Wh_s   = (const float*)d_in[4];
    const float* b_s    = (const float*)d_in[5];
    const float* W_se   = (const float*)d_in[6];
    const float* b_se   = (const float*)d_in[7];
    const float* Wx_e   = (const float*)d_in[8];
    const float* Wh_e   = (const float*)d_in[9];
    const float* b_e    = (const float*)d_in[10];
    const float* W_hk   = (const float*)d_in[11];
    const float* b_hk   = (const float*)d_in[12];
    const float* W_sd   = (const float*)d_in[13];
    const float* b_sd   = (const float*)d_in[14];
    const float* W_d1   = (const float*)d_in[15];
    const float* b_d1   = (const float*)d_in[16];
    const float* init_a = (const float*)d_in[17];
    const float* init_b = (const float*)d_in[18];

    float* xw   = sym(g_xw);
    float* Wt   = sym(g_Wt);
    float* B1   = sym(g_B1);
    float* B2   = sym(g_B2);
    float* c0   = sym(g_c0);
    float* hA   = sym(g_hA);
    float* hB   = sym(g_hB);
    float* pref = sym(g_pref);
    float* MeMs = sym(g_MeMs);
    float* pmS  = sym(g_pmS);
    float* be   = sym(g_be);
    float* bs   = sym(g_bs);
    float* S2   = sym(g_S2);
    float* uBuf = sym(g_u);
    float* hk   = sym(g_hk);
    float* wM   = sym(g_w);
    float* cX   = sym(g_cX);
    float* hX   = sym(g_hX);
    float* cY   = sym(g_cY);
    float* hY   = sym(g_hY);
    float* pX   = sym(g_pX);
    float* pY   = sym(g_pY);

    // 0) weight reshapes / merges
    wt_kernel<<<(HD * H4 + 255) / 256, 256>>>(Wh_s, Wt);
    copyB_kernel<<<(HD * NW + 255) / 256, 256>>>(Wh_e, W_hk, B1);
    copyB_kernel<<<(HD * NW + 255) / 256, 256>>>(Wx_e, W_sd, B2);

    // 1) token projection: xw = embed[ids] @ Wx_s + b_s
    mma_gemm<0><<<dim3(TOK / 64, H4 / 64), 256>>>(
        embed, ids, Wx_s, b_s, xw, TOK, H4,
        nullptr, nullptr, nullptr, nullptr, nullptr, nullptr, nullptr, nullptr, nullptr);

    // 2) statement LSTM: step 0 elementwise, steps 1-7 fused MMA
    lstm_gate0_kernel<<<(SEQS * HD + 255) / 256, 256>>>(xw, c0, hA);
    float *hs = hA, *hd = hB;
    for (int t = 1; t < TT; t++) {
        mma_gemm<1><<<dim3(SEQS / 64, H4 / 64), 256>>>(
            hs, nullptr, Wt, nullptr, nullptr, SEQS, H4,
            xw + (size_t)t * H4, c0, hd,
            nullptr, nullptr, nullptr, nullptr, nullptr, nullptr);
        float* tmp = hs; hs = hd; hd = tmp;
    }

    // 3) prefix sums
    cumsum_kernel<<<BB, HD>>>(hs, pref);

    // 4) composed tables
    mma_gemm<0><<<dim3(HD / 64, NW / 64), 256>>>(
        W_se, nullptr, B2, nullptr, MeMs, HD, NW,
        nullptr, nullptr, nullptr, nullptr, nullptr, nullptr, nullptr, nullptr, nullptr);
    mma_gemm<0><<<dim3((ROWS + 63) / 64, NW / 64), 256>>>(
        pref, nullptr, MeMs, nullptr, pmS, ROWS, NW,
        nullptr, nullptr, nullptr, nullptr, nullptr, nullptr, nullptr, nullptr, nullptr);
    vecmat_kernel<<<(H4 + 255) / 256, 256>>>(b_se, Wx_e, b_e, be, HD, H4);
    vecmat_kernel<<<1, 256>>>(b_se, W_sd, b_sd, bs, HD, HD);

    // 5) layer-invariant logit term + exec init
    s2_kernel<<<ROWS, 128>>>(pmS, bs, W_d1, S2);
    init_exec_kernel<<<ROWS, 256>>>(init_a, init_b, cX, hX, pX);

    // 6) execution layers
    float *cS = cX, *hS = hX, *pS = pX, *cD = cY, *hD2 = hY, *pD = pY;
    for (int layer = 0; layer < NLAY; layer++) {
        mma_gemm<2><<<dim3((ROWS + 63) / 64, NW / 64), 256>>>(
            hS, nullptr, B1, nullptr, nullptr, ROWS, NW,
            nullptr, nullptr, nullptr,
            be, pmS, b_hk, W_d1, uBuf, hk);
        softmax_kernel<<<ROWS, 256>>>(hk, S2, b_d1, pS, clen, layer, wM);
        float* hOutPtr = (layer == NLAY - 1) ? (float*)d_out : hD2;
        agg_kernel<<<ROWS, 256>>>(wM, pmS, uBuf, cS, hS, cD, hOutPtr, pD);
        float* t;
        t = cS; cS = cD; cD = t;
        t = hS; hS = hD2; hD2 = t;
        t = pS; pS = pD; pD = t;
    }
}